// round 2
// baseline (speedup 1.0000x reference)
#include <cuda_runtime.h>
#include <math.h>

#define BSZ 2048
#define NTOT 4096
#define DDIM 256
#define INV_T 2.0f      // 1 / temperature (0.5)

#define BM 128
#define BN 128
#define BK 16

// Scratch (device globals: no allocation allowed in kernel_launch)
__device__ float g_zn[NTOT * DDIM];   // normalized rows
__device__ float g_rowsum[NTOT];      // sum_j!=i exp(2*dot - 2)
__device__ float g_pos[NTOT];         // positive-pair logit per row

// ---------------------------------------------------------------------------
// Kernel 1: row L2-normalize (one warp per row) + zero rowsum accumulators
// ---------------------------------------------------------------------------
__global__ __launch_bounds__(256) void nt_normalize(const float* __restrict__ zi,
                                                    const float* __restrict__ zj) {
    int gwarp = (blockIdx.x * blockDim.x + threadIdx.x) >> 5;   // row id
    int lane  = threadIdx.x & 31;
    if (gwarp >= NTOT) return;

    const float* src = (gwarp < BSZ) ? (zi + (size_t)gwarp * DDIM)
                                     : (zj + (size_t)(gwarp - BSZ) * DDIM);
    const float4* src4 = (const float4*)src;
    float4 a = src4[lane];
    float4 b = src4[lane + 32];

    float ss = a.x * a.x + a.y * a.y + a.z * a.z + a.w * a.w
             + b.x * b.x + b.y * b.y + b.z * b.z + b.w * b.w;
#pragma unroll
    for (int o = 16; o; o >>= 1) ss += __shfl_xor_sync(0xFFFFFFFFu, ss, o);

    float norm = fmaxf(sqrtf(ss), 1e-8f);
    float inv = 1.0f / norm;

    float4* dst4 = (float4*)(g_zn + (size_t)gwarp * DDIM);
    a.x *= inv; a.y *= inv; a.z *= inv; a.w *= inv;
    b.x *= inv; b.y *= inv; b.z *= inv; b.w *= inv;
    dst4[lane]      = a;
    dst4[lane + 32] = b;

    if (lane == 0) g_rowsum[gwarp] = 0.0f;
}

// ---------------------------------------------------------------------------
// Kernel 2: tiled S = zn @ zn^T with fused exp-row-sum epilogue.
// 128x128 tile per block, 256 threads, 8x8 register tile per thread.
// ---------------------------------------------------------------------------
__global__ __launch_bounds__(256) void nt_tile() {
    __shared__ float As[BK][BM + 4];
    __shared__ float Bs[BK][BN + 4];

    int tid = threadIdx.x;
    int tx = tid & 15;          // column group
    int ty = tid >> 4;          // row group
    int rowBase = blockIdx.y * BM;
    int colBase = blockIdx.x * BN;

    float acc[8][8];
#pragma unroll
    for (int i = 0; i < 8; i++)
#pragma unroll
        for (int j = 0; j < 8; j++) acc[i][j] = 0.0f;

    for (int k0 = 0; k0 < DDIM; k0 += BK) {
        // load A and B tiles: 512 float4 each, 2 per thread per matrix
#pragma unroll
        for (int l = 0; l < 2; l++) {
            int f  = tid + l * 256;   // float4 index in [0,512)
            int r  = f >> 2;          // row within tile
            int kq = (f & 3) << 2;    // k offset (0,4,8,12)
            float4 va = *(const float4*)(g_zn + (size_t)(rowBase + r) * DDIM + k0 + kq);
            As[kq + 0][r] = va.x; As[kq + 1][r] = va.y;
            As[kq + 2][r] = va.z; As[kq + 3][r] = va.w;
            float4 vb = *(const float4*)(g_zn + (size_t)(colBase + r) * DDIM + k0 + kq);
            Bs[kq + 0][r] = vb.x; Bs[kq + 1][r] = vb.y;
            Bs[kq + 2][r] = vb.z; Bs[kq + 3][r] = vb.w;
        }
        __syncthreads();

#pragma unroll
        for (int k = 0; k < BK; k++) {
            float a[8], b[8];
            *(float4*)(a)     = *(const float4*)&As[k][ty * 8];
            *(float4*)(a + 4) = *(const float4*)&As[k][ty * 8 + 4];
            *(float4*)(b)     = *(const float4*)&Bs[k][tx * 8];
            *(float4*)(b + 4) = *(const float4*)&Bs[k][tx * 8 + 4];
#pragma unroll
            for (int i = 0; i < 8; i++)
#pragma unroll
                for (int j = 0; j < 8; j++)
                    acc[i][j] = fmaf(a[i], b[j], acc[i][j]);
        }
        __syncthreads();
    }

    // Epilogue: logits = acc * 2; term = exp(logit - 2), skip diagonal,
    // capture positive-pair logit.
    float rsum[8];
#pragma unroll
    for (int i = 0; i < 8; i++) {
        int row = rowBase + ty * 8 + i;
        int partner = (row < BSZ) ? (row + BSZ) : (row - BSZ);
        float s = 0.0f;
#pragma unroll
        for (int j = 0; j < 8; j++) {
            int col = colBase + tx * 8 + j;
            float v = acc[i][j] * INV_T;
            if (col == partner) g_pos[row] = v;
            if (col != row) s += __expf(v - 2.0f);
        }
        rsum[i] = s;
    }

    // Reduce across the 16 tx lanes (they sit in one half-warp: lane = (ty&1)*16+tx)
#pragma unroll
    for (int i = 0; i < 8; i++) {
        float s = rsum[i];
#pragma unroll
        for (int o = 8; o; o >>= 1) s += __shfl_xor_sync(0xFFFFFFFFu, s, o);
        if (tx == 0) atomicAdd(&g_rowsum[rowBase + ty * 8 + i], s);
    }
}

// ---------------------------------------------------------------------------
// Kernel 3: loss = mean_i ( 2 + log(rowsum_i) - pos_i )
// ---------------------------------------------------------------------------
__global__ __launch_bounds__(256) void nt_finalize(float* __restrict__ out) {
    __shared__ float sbuf[256];
    float s = 0.0f;
    for (int i = threadIdx.x; i < NTOT; i += 256)
        s += 2.0f + logf(g_rowsum[i]) - g_pos[i];
    sbuf[threadIdx.x] = s;
    __syncthreads();
#pragma unroll
    for (int o = 128; o; o >>= 1) {
        if (threadIdx.x < o) sbuf[threadIdx.x] += sbuf[threadIdx.x + o];
        __syncthreads();
    }
    if (threadIdx.x == 0) out[0] = sbuf[0] * (1.0f / NTOT);
}

extern "C" void kernel_launch(void* const* d_in, const int* in_sizes, int n_in,
                              void* d_out, int out_size) {
    const float* zi = (const float*)d_in[0];
    const float* zj = (const float*)d_in[1];
    float* out = (float*)d_out;
    (void)in_sizes; (void)n_in; (void)out_size;

    nt_normalize<<<NTOT / 8, 256>>>(zi, zj);            // 512 blocks, 1 warp/row
    nt_tile<<<dim3(NTOT / BN, NTOT / BM), 256>>>();     // 32x32 tiles
    nt_finalize<<<1, 256>>>(out);
}

// round 4
// speedup vs baseline: 4.0968x; 4.0968x over previous
#include <cuda_runtime.h>
#include <cuda_bf16.h>
#include <cstdint>
#include <math.h>

#define BSZ 2048
#define NTOT 4096
#define DDIM 256
#define INV_T 2.0f          // 1 / temperature
#define PITCH 40            // smem row pitch in bf16 (80 B) -> conflict-free ldmatrix
#define BK 32               // k per stage

// Scratch (device globals; no allocation allowed)
__device__ uint4 g_znb4[NTOT * DDIM / 8];   // normalized rows, bf16, 16B-aligned
__device__ float g_rowsum[NTOT];
__device__ float g_pos[NTOT];

// ---------------------------------------------------------------------------
// Kernel 1: L2-normalize rows -> bf16; zero rowsum accumulators
// ---------------------------------------------------------------------------
__global__ __launch_bounds__(256) void nt_normalize(const float* __restrict__ zi,
                                                    const float* __restrict__ zj) {
    int row  = (blockIdx.x * blockDim.x + threadIdx.x) >> 5;
    int lane = threadIdx.x & 31;
    if (row >= NTOT) return;

    const float* src = (row < BSZ) ? (zi + (size_t)row * DDIM)
                                   : (zj + (size_t)(row - BSZ) * DDIM);
    const float4* src4 = (const float4*)src;
    float4 a = src4[lane];
    float4 b = src4[lane + 32];

    float ss = a.x*a.x + a.y*a.y + a.z*a.z + a.w*a.w
             + b.x*b.x + b.y*b.y + b.z*b.z + b.w*b.w;
#pragma unroll
    for (int o = 16; o; o >>= 1) ss += __shfl_xor_sync(0xFFFFFFFFu, ss, o);

    float inv = 1.0f / fmaxf(sqrtf(ss), 1e-8f);

    __nv_bfloat16* dst = (__nv_bfloat16*)g_znb4 + (size_t)row * DDIM;
    __nv_bfloat162* d2 = (__nv_bfloat162*)dst;
    d2[2*lane]          = __nv_bfloat162(__float2bfloat16(a.x*inv), __float2bfloat16(a.y*inv));
    d2[2*lane + 1]      = __nv_bfloat162(__float2bfloat16(a.z*inv), __float2bfloat16(a.w*inv));
    d2[64 + 2*lane]     = __nv_bfloat162(__float2bfloat16(b.x*inv), __float2bfloat16(b.y*inv));
    d2[64 + 2*lane + 1] = __nv_bfloat162(__float2bfloat16(b.z*inv), __float2bfloat16(b.w*inv));

    if (lane == 0) g_rowsum[row] = 0.0f;
}

// ---------------------------------------------------------------------------
// Helpers
// ---------------------------------------------------------------------------
__device__ __forceinline__ void cp_async16(uint32_t smem_addr, const void* gptr) {
    asm volatile("cp.async.cg.shared.global [%0], [%1], 16;\n"
                 :: "r"(smem_addr), "l"(gptr));
}
__device__ __forceinline__ void cp_commit() {
    asm volatile("cp.async.commit_group;\n");
}
__device__ __forceinline__ void cp_wait1() {
    asm volatile("cp.async.wait_group 1;\n");
}
__device__ __forceinline__ void cp_wait0() {
    asm volatile("cp.async.wait_group 0;\n");
}
__device__ __forceinline__ void ldm_x4(uint32_t addr, uint32_t& r0, uint32_t& r1,
                                       uint32_t& r2, uint32_t& r3) {
    asm volatile("ldmatrix.sync.aligned.m8n8.x4.shared.b16 {%0,%1,%2,%3}, [%4];\n"
                 : "=r"(r0), "=r"(r1), "=r"(r2), "=r"(r3) : "r"(addr));
}
__device__ __forceinline__ void mma16816(float& d0, float& d1, float& d2, float& d3,
                                         uint32_t a0, uint32_t a1, uint32_t a2, uint32_t a3,
                                         uint32_t b0, uint32_t b1) {
    asm volatile("mma.sync.aligned.m16n8k16.row.col.f32.bf16.bf16.f32 "
                 "{%0,%1,%2,%3}, {%4,%5,%6,%7}, {%8,%9}, {%0,%1,%2,%3};\n"
                 : "+f"(d0), "+f"(d1), "+f"(d2), "+f"(d3)
                 : "r"(a0), "r"(a1), "r"(a2), "r"(a3), "r"(b0), "r"(b1));
}

// ---------------------------------------------------------------------------
// Kernel 2: bf16 tensor-core GEMM (S = zn @ zn^T) with fused exp-rowsum epilogue.
// CTA tile 128x128, 8 warps (4 m x 2 n), warp tile 32x64, BK=32 double-buffered.
// ---------------------------------------------------------------------------
__global__ __launch_bounds__(256) void nt_mma() {
    __shared__ __align__(16) __nv_bfloat16 sA[2][128 * PITCH];
    __shared__ __align__(16) __nv_bfloat16 sB[2][128 * PITCH];

    const int tid  = threadIdx.x;
    const int wid  = tid >> 5;
    const int lane = tid & 31;
    const int warp_m = wid & 3;      // 0..3 -> 32 rows each
    const int warp_n = wid >> 2;     // 0..1 -> 64 cols each
    const int rowBase = blockIdx.y * 128;
    const int colBase = blockIdx.x * 128;

    const __nv_bfloat16* Z = (const __nv_bfloat16*)g_znb4;

    float acc[2][8][4];
#pragma unroll
    for (int mi = 0; mi < 2; mi++)
#pragma unroll
        for (int ni = 0; ni < 8; ni++)
#pragma unroll
            for (int r = 0; r < 4; r++) acc[mi][ni][r] = 0.0f;

    // Per-thread load assignment: 2 chunks for A, 2 for B (16B each)
    const int ch0 = tid, ch1 = tid + 256;
    const int rA0 = ch0 >> 2, cA0 = ch0 & 3;
    const int rA1 = ch1 >> 2, cA1 = ch1 & 3;

    auto load_stage = [&](int s, int kt) {
        int kb = kt * BK;
        uint32_t dA0 = (uint32_t)__cvta_generic_to_shared(&sA[s][rA0 * PITCH + cA0 * 8]);
        uint32_t dA1 = (uint32_t)__cvta_generic_to_shared(&sA[s][rA1 * PITCH + cA1 * 8]);
        uint32_t dB0 = (uint32_t)__cvta_generic_to_shared(&sB[s][rA0 * PITCH + cA0 * 8]);
        uint32_t dB1 = (uint32_t)__cvta_generic_to_shared(&sB[s][rA1 * PITCH + cA1 * 8]);
        cp_async16(dA0, Z + (size_t)(rowBase + rA0) * DDIM + kb + cA0 * 8);
        cp_async16(dA1, Z + (size_t)(rowBase + rA1) * DDIM + kb + cA1 * 8);
        cp_async16(dB0, Z + (size_t)(colBase + rA0) * DDIM + kb + cA0 * 8);
        cp_async16(dB1, Z + (size_t)(colBase + rA1) * DDIM + kb + cA1 * 8);
        cp_commit();
    };

    const int NKT = DDIM / BK;   // 8 stages
    load_stage(0, 0);

    for (int kt = 0; kt < NKT; kt++) {
        if (kt + 1 < NKT) { load_stage((kt + 1) & 1, kt + 1); cp_wait1(); }
        else              { cp_wait0(); }
        __syncthreads();

        const int s = kt & 1;
#pragma unroll
        for (int ks = 0; ks < 2; ks++) {       // two k16 sub-steps
            const int k16 = ks * 16;
            // A fragments (2 m-tiles)
            uint32_t a[2][4];
#pragma unroll
            for (int mi = 0; mi < 2; mi++) {
                int r = warp_m * 32 + mi * 16 + (lane & 15);
                uint32_t ad = (uint32_t)__cvta_generic_to_shared(
                    &sA[s][r * PITCH + k16 + (lane >> 4) * 8]);
                ldm_x4(ad, a[mi][0], a[mi][1], a[mi][2], a[mi][3]);
            }
            // B fragments (8 n-tiles via 4 x4 loads)
            uint32_t b[8][2];
#pragma unroll
            for (int p = 0; p < 4; p++) {
                int nrow = warp_n * 64 + p * 16 + (lane >> 4) * 8 + (lane & 7);
                uint32_t ad = (uint32_t)__cvta_generic_to_shared(
                    &sB[s][nrow * PITCH + k16 + ((lane >> 3) & 1) * 8]);
                uint32_t r0, r1, r2, r3;
                ldm_x4(ad, r0, r1, r2, r3);
                b[2*p][0] = r0; b[2*p][1] = r1;
                b[2*p+1][0] = r2; b[2*p+1][1] = r3;
            }
#pragma unroll
            for (int mi = 0; mi < 2; mi++)
#pragma unroll
                for (int ni = 0; ni < 8; ni++)
                    mma16816(acc[mi][ni][0], acc[mi][ni][1], acc[mi][ni][2], acc[mi][ni][3],
                             a[mi][0], a[mi][1], a[mi][2], a[mi][3],
                             b[ni][0], b[ni][1]);
        }
        __syncthreads();
    }

    // ---- Epilogue: logits = 2*dot; term = exp(logit - 2); skip diag; capture pos
    // C fragment: lane owns rows (lane>>2) and (lane>>2)+8; cols 2*(lane&3)+{0,1}
    float rs[2][2] = {{0.f, 0.f}, {0.f, 0.f}};   // [mi][upper/lower 8-row half]
#pragma unroll
    for (int mi = 0; mi < 2; mi++) {
#pragma unroll
        for (int half = 0; half < 2; half++) {
            int row = rowBase + warp_m * 32 + mi * 16 + half * 8 + (lane >> 2);
            int partner = (row < BSZ) ? (row + BSZ) : (row - BSZ);
            float s = 0.0f;
#pragma unroll
            for (int ni = 0; ni < 8; ni++) {
#pragma unroll
                for (int cc = 0; cc < 2; cc++) {
                    int col = colBase + warp_n * 64 + ni * 8 + 2 * (lane & 3) + cc;
                    float v = acc[mi][ni][half * 2 + cc] * INV_T;
                    if (col == partner) g_pos[row] = v;
                    if (col != row) s += __expf(v - 2.0f);
                }
            }
            rs[mi][half] = s;
        }
    }
    // Reduce across the 4 lanes sharing each row, then atomic per row
#pragma unroll
    for (int mi = 0; mi < 2; mi++)
#pragma unroll
        for (int half = 0; half < 2; half++) {
            float s = rs[mi][half];
            s += __shfl_xor_sync(0xFFFFFFFFu, s, 1);
            s += __shfl_xor_sync(0xFFFFFFFFu, s, 2);
            if ((lane & 3) == 0) {
                int row = rowBase + warp_m * 32 + mi * 16 + half * 8 + (lane >> 2);
                atomicAdd(&g_rowsum[row], s);
            }
        }
}

// ---------------------------------------------------------------------------
// Kernel 3: loss = mean_i ( 2 + log(rowsum_i) - pos_i )
// ---------------------------------------------------------------------------
__global__ __launch_bounds__(256) void nt_finalize(float* __restrict__ out) {
    __shared__ float sbuf[256];
    float s = 0.0f;
    for (int i = threadIdx.x; i < NTOT; i += 256)
        s += 2.0f + logf(g_rowsum[i]) - g_pos[i];
    sbuf[threadIdx.x] = s;
    __syncthreads();
#pragma unroll
    for (int o = 128; o; o >>= 1) {
        if (threadIdx.x < o) sbuf[threadIdx.x] += sbuf[threadIdx.x + o];
        __syncthreads();
    }
    if (threadIdx.x == 0) out[0] = sbuf[0] * (1.0f / NTOT);
}

extern "C" void kernel_launch(void* const* d_in, const int* in_sizes, int n_in,
                              void* d_out, int out_size) {
    const float* zi = (const float*)d_in[0];
    const float* zj = (const float*)d_in[1];
    float* out = (float*)d_out;
    (void)in_sizes; (void)n_in; (void)out_size;

    nt_normalize<<<NTOT / 8, 256>>>(zi, zj);
    nt_mma<<<dim3(NTOT / 128, NTOT / 128), 256>>>();
    nt_finalize<<<1, 256>>>(out);
}

// round 5
// speedup vs baseline: 5.8615x; 1.4308x over previous
#include <cuda_runtime.h>
#include <cuda_bf16.h>
#include <cstdint>
#include <math.h>

#define BSZ 2048
#define NTOT 4096
#define DDIM 256
#define INV_T 2.0f          // 1 / temperature
#define PITCH 40            // smem row pitch in bf16 (80 B) -> conflict-free ldmatrix
#define BK 32               // k per stage
#define NTILE 32            // 4096 / 128 tiles per dim
#define NTRI (NTILE * (NTILE + 1) / 2)   // 528 upper-triangular tiles

// Scratch (device globals; no allocation allowed)
__device__ uint4 g_znb4[NTOT * DDIM / 8];   // normalized rows, bf16, 16B-aligned
__device__ float g_rowsum[NTOT];
__device__ float g_pos[NTOT];

// ---------------------------------------------------------------------------
// Kernel 1: L2-normalize rows -> bf16; zero rowsum accumulators
// ---------------------------------------------------------------------------
__global__ __launch_bounds__(256) void nt_normalize(const float* __restrict__ zi,
                                                    const float* __restrict__ zj) {
    int row  = (blockIdx.x * blockDim.x + threadIdx.x) >> 5;
    int lane = threadIdx.x & 31;
    if (row >= NTOT) return;

    const float* src = (row < BSZ) ? (zi + (size_t)row * DDIM)
                                   : (zj + (size_t)(row - BSZ) * DDIM);
    const float4* src4 = (const float4*)src;
    float4 a = src4[lane];
    float4 b = src4[lane + 32];

    float ss = a.x*a.x + a.y*a.y + a.z*a.z + a.w*a.w
             + b.x*b.x + b.y*b.y + b.z*b.z + b.w*b.w;
#pragma unroll
    for (int o = 16; o; o >>= 1) ss += __shfl_xor_sync(0xFFFFFFFFu, ss, o);

    float inv = 1.0f / fmaxf(sqrtf(ss), 1e-8f);

    __nv_bfloat16* dst = (__nv_bfloat16*)g_znb4 + (size_t)row * DDIM;
    __nv_bfloat162* d2 = (__nv_bfloat162*)dst;
    d2[2*lane]          = __nv_bfloat162(__float2bfloat16(a.x*inv), __float2bfloat16(a.y*inv));
    d2[2*lane + 1]      = __nv_bfloat162(__float2bfloat16(a.z*inv), __float2bfloat16(a.w*inv));
    d2[64 + 2*lane]     = __nv_bfloat162(__float2bfloat16(b.x*inv), __float2bfloat16(b.y*inv));
    d2[64 + 2*lane + 1] = __nv_bfloat162(__float2bfloat16(b.z*inv), __float2bfloat16(b.w*inv));

    if (lane == 0) g_rowsum[row] = 0.0f;
}

// ---------------------------------------------------------------------------
// Helpers
// ---------------------------------------------------------------------------
__device__ __forceinline__ void cp_async16(uint32_t smem_addr, const void* gptr) {
    asm volatile("cp.async.cg.shared.global [%0], [%1], 16;\n"
                 :: "r"(smem_addr), "l"(gptr));
}
__device__ __forceinline__ void cp_commit() {
    asm volatile("cp.async.commit_group;\n");
}
__device__ __forceinline__ void cp_wait1() {
    asm volatile("cp.async.wait_group 1;\n");
}
__device__ __forceinline__ void cp_wait0() {
    asm volatile("cp.async.wait_group 0;\n");
}
__device__ __forceinline__ void ldm_x4(uint32_t addr, uint32_t& r0, uint32_t& r1,
                                       uint32_t& r2, uint32_t& r3) {
    asm volatile("ldmatrix.sync.aligned.m8n8.x4.shared.b16 {%0,%1,%2,%3}, [%4];\n"
                 : "=r"(r0), "=r"(r1), "=r"(r2), "=r"(r3) : "r"(addr));
}
__device__ __forceinline__ void mma16816(float& d0, float& d1, float& d2, float& d3,
                                         uint32_t a0, uint32_t a1, uint32_t a2, uint32_t a3,
                                         uint32_t b0, uint32_t b1) {
    asm volatile("mma.sync.aligned.m16n8k16.row.col.f32.bf16.bf16.f32 "
                 "{%0,%1,%2,%3}, {%4,%5,%6,%7}, {%8,%9}, {%0,%1,%2,%3};\n"
                 : "+f"(d0), "+f"(d1), "+f"(d2), "+f"(d3)
                 : "r"(a0), "r"(a1), "r"(a2), "r"(a3), "r"(b0), "r"(b1));
}

// ---------------------------------------------------------------------------
// Kernel 2: bf16 tensor-core GEMM on UPPER-TRIANGULAR tiles only (S symmetric).
// Off-diagonal tiles contribute row-sums AND column-sums (transpose image).
// CTA tile 128x128, 8 warps (4 m x 2 n), warp tile 32x64, BK=32 double-buffered.
// ---------------------------------------------------------------------------
__global__ __launch_bounds__(256) void nt_mma() {
    __shared__ __align__(16) __nv_bfloat16 sA[2][128 * PITCH];
    __shared__ __align__(16) __nv_bfloat16 sB[2][128 * PITCH];

    // Decode upper-triangular tile index -> (bi, bj), bi <= bj
    int t = blockIdx.x;
    int bi = 0;
    {
        int rem = t;
        while (rem >= NTILE - bi) { rem -= NTILE - bi; bi++; }
        t = rem;            // now t = bj - bi
    }
    const int bj = bi + t;
    const bool diag = (bi == bj);
    const int rowBase = bi * 128;
    const int colBase = bj * 128;

    const int tid  = threadIdx.x;
    const int wid  = tid >> 5;
    const int lane = tid & 31;
    const int warp_m = wid & 3;      // 0..3 -> 32 rows each
    const int warp_n = wid >> 2;     // 0..1 -> 64 cols each

    const __nv_bfloat16* Z = (const __nv_bfloat16*)g_znb4;

    float acc[2][8][4];
#pragma unroll
    for (int mi = 0; mi < 2; mi++)
#pragma unroll
        for (int ni = 0; ni < 8; ni++)
#pragma unroll
            for (int r = 0; r < 4; r++) acc[mi][ni][r] = 0.0f;

    const int ch0 = tid, ch1 = tid + 256;
    const int rA0 = ch0 >> 2, cA0 = ch0 & 3;
    const int rA1 = ch1 >> 2, cA1 = ch1 & 3;

    auto load_stage = [&](int s, int kt) {
        int kb = kt * BK;
        uint32_t dA0 = (uint32_t)__cvta_generic_to_shared(&sA[s][rA0 * PITCH + cA0 * 8]);
        uint32_t dA1 = (uint32_t)__cvta_generic_to_shared(&sA[s][rA1 * PITCH + cA1 * 8]);
        uint32_t dB0 = (uint32_t)__cvta_generic_to_shared(&sB[s][rA0 * PITCH + cA0 * 8]);
        uint32_t dB1 = (uint32_t)__cvta_generic_to_shared(&sB[s][rA1 * PITCH + cA1 * 8]);
        cp_async16(dA0, Z + (size_t)(rowBase + rA0) * DDIM + kb + cA0 * 8);
        cp_async16(dA1, Z + (size_t)(rowBase + rA1) * DDIM + kb + cA1 * 8);
        cp_async16(dB0, Z + (size_t)(colBase + rA0) * DDIM + kb + cA0 * 8);
        cp_async16(dB1, Z + (size_t)(colBase + rA1) * DDIM + kb + cA1 * 8);
        cp_commit();
    };

    const int NKT = DDIM / BK;   // 8 stages
    load_stage(0, 0);

    for (int kt = 0; kt < NKT; kt++) {
        if (kt + 1 < NKT) { load_stage((kt + 1) & 1, kt + 1); cp_wait1(); }
        else              { cp_wait0(); }
        __syncthreads();

        const int s = kt & 1;
#pragma unroll
        for (int ks = 0; ks < 2; ks++) {       // two k16 sub-steps
            const int k16 = ks * 16;
            uint32_t a[2][4];
#pragma unroll
            for (int mi = 0; mi < 2; mi++) {
                int r = warp_m * 32 + mi * 16 + (lane & 15);
                uint32_t ad = (uint32_t)__cvta_generic_to_shared(
                    &sA[s][r * PITCH + k16 + (lane >> 4) * 8]);
                ldm_x4(ad, a[mi][0], a[mi][1], a[mi][2], a[mi][3]);
            }
            uint32_t b[8][2];
#pragma unroll
            for (int p = 0; p < 4; p++) {
                int nrow = warp_n * 64 + p * 16 + (lane >> 4) * 8 + (lane & 7);
                uint32_t ad = (uint32_t)__cvta_generic_to_shared(
                    &sB[s][nrow * PITCH + k16 + ((lane >> 3) & 1) * 8]);
                uint32_t r0, r1, r2, r3;
                ldm_x4(ad, r0, r1, r2, r3);
                b[2*p][0] = r0; b[2*p][1] = r1;
                b[2*p+1][0] = r2; b[2*p+1][1] = r3;
            }
#pragma unroll
            for (int mi = 0; mi < 2; mi++)
#pragma unroll
                for (int ni = 0; ni < 8; ni++)
                    mma16816(acc[mi][ni][0], acc[mi][ni][1], acc[mi][ni][2], acc[mi][ni][3],
                             a[mi][0], a[mi][1], a[mi][2], a[mi][3],
                             b[ni][0], b[ni][1]);
        }
        __syncthreads();
    }

    // ---- Epilogue.
    // C fragment: lane owns rows (lane>>2), (lane>>2)+8 per 16-row tile;
    // cols 2*(lane&3)+{0,1} per 8-col tile.
    // Row sums always; column sums additionally on off-diagonal tiles (transpose
    // image of this tile). Positive pair: col == row + BSZ (always upper tri).
    float colsum[8][2];
#pragma unroll
    for (int ni = 0; ni < 8; ni++) { colsum[ni][0] = 0.0f; colsum[ni][1] = 0.0f; }

#pragma unroll
    for (int mi = 0; mi < 2; mi++) {
#pragma unroll
        for (int half = 0; half < 2; half++) {
            int row = rowBase + warp_m * 32 + mi * 16 + half * 8 + (lane >> 2);
            float s = 0.0f;
#pragma unroll
            for (int ni = 0; ni < 8; ni++) {
#pragma unroll
                for (int cc = 0; cc < 2; cc++) {
                    int col = colBase + warp_n * 64 + ni * 8 + 2 * (lane & 3) + cc;
                    float v = acc[mi][ni][half * 2 + cc] * INV_T;
                    if (col == row + BSZ) { g_pos[row] = v; g_pos[col] = v; }
                    float e = __expf(v - 2.0f);
                    if (!diag || col != row) s += e;
                    colsum[ni][cc] += e;     // only used when !diag
                }
            }
            // reduce row sum across the 4 lanes sharing this row
            s += __shfl_xor_sync(0xFFFFFFFFu, s, 1);
            s += __shfl_xor_sync(0xFFFFFFFFu, s, 2);
            if ((lane & 3) == 0) atomicAdd(&g_rowsum[row], s);
        }
    }

    if (!diag) {
        // Column sums: reduce over the 8 lanes sharing each column (same lane&3),
        // i.e. shfl over lane bits 2..4. All contribute to rowsum[col] via symmetry.
#pragma unroll
        for (int ni = 0; ni < 8; ni++) {
#pragma unroll
            for (int cc = 0; cc < 2; cc++) {
                float s = colsum[ni][cc];
                s += __shfl_xor_sync(0xFFFFFFFFu, s, 4);
                s += __shfl_xor_sync(0xFFFFFFFFu, s, 8);
                s += __shfl_xor_sync(0xFFFFFFFFu, s, 16);
                if (lane < 4) {
                    int col = colBase + warp_n * 64 + ni * 8 + 2 * lane + cc;
                    atomicAdd(&g_rowsum[col], s);
                }
            }
        }
    }
}

// ---------------------------------------------------------------------------
// Kernel 3: loss = mean_i ( 2 + log(rowsum_i) - pos_i )
// ---------------------------------------------------------------------------
__global__ __launch_bounds__(256) void nt_finalize(float* __restrict__ out) {
    __shared__ float sbuf[256];
    float s = 0.0f;
    for (int i = threadIdx.x; i < NTOT; i += 256)
        s += 2.0f + logf(g_rowsum[i]) - g_pos[i];
    sbuf[threadIdx.x] = s;
    __syncthreads();
#pragma unroll
    for (int o = 128; o; o >>= 1) {
        if (threadIdx.x < o) sbuf[threadIdx.x] += sbuf[threadIdx.x + o];
        __syncthreads();
    }
    if (threadIdx.x == 0) out[0] = sbuf[0] * (1.0f / NTOT);
}

extern "C" void kernel_launch(void* const* d_in, const int* in_sizes, int n_in,
                              void* d_out, int out_size) {
    const float* zi = (const float*)d_in[0];
    const float* zj = (const float*)d_in[1];
    float* out = (float*)d_out;
    (void)in_sizes; (void)n_in; (void)out_size;

    nt_normalize<<<NTOT / 8, 256>>>(zi, zj);
    nt_mma<<<NTRI, 256>>>();
    nt_finalize<<<1, 256>>>(out);
}

// round 7
// speedup vs baseline: 6.2459x; 1.0656x over previous
#include <cuda_runtime.h>
#include <cuda_bf16.h>
#include <cstdint>
#include <math.h>

#define BSZ   2048
#define NTOT  4096
#define DDIM  256
#define INV_T 2.0f
#define NTILE 32
#define NTRI  528            // upper-triangular 128x128 tiles
#define BKS   64             // K per stage
#define NKT   4              // DDIM / BKS
#define STG   16384          // 128 rows * 128 B per stage buffer
// dynamic smem: A[2 stages] then B[2 stages]
#define OFF_A 0
#define OFF_B (2 * STG)
#define SMEM_TOTAL (4 * STG)

// Scratch (device globals; no allocation allowed)
__device__ uint4  g_znb4[NTOT * DDIM / 8];
__device__ float  g_rowsum[NTOT];
__device__ float  g_pos[NTOT];
__device__ unsigned g_done;

// ---------------------------------------------------------------------------
// Kernel 1: L2-normalize rows -> bf16; zero accumulators + completion counter
// ---------------------------------------------------------------------------
__global__ __launch_bounds__(256) void nt_normalize(const float* __restrict__ zi,
                                                    const float* __restrict__ zj) {
    int row  = (blockIdx.x * blockDim.x + threadIdx.x) >> 5;
    int lane = threadIdx.x & 31;
    if (blockIdx.x == 0 && threadIdx.x == 0) g_done = 0u;
    if (row >= NTOT) return;

    const float* src = (row < BSZ) ? (zi + (size_t)row * DDIM)
                                   : (zj + (size_t)(row - BSZ) * DDIM);
    const float4* s4 = (const float4*)src;
    float4 a = s4[lane];
    float4 b = s4[lane + 32];

    float ss = a.x*a.x + a.y*a.y + a.z*a.z + a.w*a.w
             + b.x*b.x + b.y*b.y + b.z*b.z + b.w*b.w;
#pragma unroll
    for (int o = 16; o; o >>= 1) ss += __shfl_xor_sync(0xFFFFFFFFu, ss, o);

    float inv = 1.0f / fmaxf(sqrtf(ss), 1e-8f);

    __nv_bfloat162* d2 = (__nv_bfloat162*)((__nv_bfloat16*)g_znb4 + (size_t)row * DDIM);
    d2[2*lane]          = __nv_bfloat162(__float2bfloat16(a.x*inv), __float2bfloat16(a.y*inv));
    d2[2*lane + 1]      = __nv_bfloat162(__float2bfloat16(a.z*inv), __float2bfloat16(a.w*inv));
    d2[64 + 2*lane]     = __nv_bfloat162(__float2bfloat16(b.x*inv), __float2bfloat16(b.y*inv));
    d2[64 + 2*lane + 1] = __nv_bfloat162(__float2bfloat16(b.z*inv), __float2bfloat16(b.w*inv));

    if (lane == 0) g_rowsum[row] = 0.0f;
}

// ---------------------------------------------------------------------------
// Helpers
// ---------------------------------------------------------------------------
__device__ __forceinline__ void cp_async16(uint32_t s, const void* g) {
    asm volatile("cp.async.cg.shared.global [%0], [%1], 16;\n" :: "r"(s), "l"(g));
}
__device__ __forceinline__ void cp_commit() { asm volatile("cp.async.commit_group;\n"); }
__device__ __forceinline__ void cp_wait1()  { asm volatile("cp.async.wait_group 1;\n"); }
__device__ __forceinline__ void cp_wait0()  { asm volatile("cp.async.wait_group 0;\n"); }
__device__ __forceinline__ void ldm_x4(uint32_t addr, uint32_t& r0, uint32_t& r1,
                                       uint32_t& r2, uint32_t& r3) {
    asm volatile("ldmatrix.sync.aligned.m8n8.x4.shared.b16 {%0,%1,%2,%3}, [%4];\n"
                 : "=r"(r0), "=r"(r1), "=r"(r2), "=r"(r3) : "r"(addr));
}
__device__ __forceinline__ void mma16816(float& d0, float& d1, float& d2, float& d3,
                                         uint32_t a0, uint32_t a1, uint32_t a2, uint32_t a3,
                                         uint32_t b0, uint32_t b1) {
    asm volatile("mma.sync.aligned.m16n8k16.row.col.f32.bf16.bf16.f32 "
                 "{%0,%1,%2,%3}, {%4,%5,%6,%7}, {%8,%9}, {%0,%1,%2,%3};\n"
                 : "+f"(d0), "+f"(d1), "+f"(d2), "+f"(d3)
                 : "r"(a0), "r"(a1), "r"(a2), "r"(a3), "r"(b0), "r"(b1));
}
__device__ __forceinline__ uint32_t sw128(uint32_t off) {   // 16B-granular XOR swizzle
    return off ^ ((off >> 3) & 0x70);
}

// ---------------------------------------------------------------------------
// Kernel 2: bf16 mma.sync GEMM on upper-triangular tiles, SW128 smem, BK=64,
// fused exp/rowsum/colsum epilogue + last-CTA finalize.
// ---------------------------------------------------------------------------
__global__ __launch_bounds__(256, 2) void nt_mma(float* __restrict__ out) {
    extern __shared__ __align__(1024) char smem[];
    uint32_t sb;
    asm("{ .reg .u64 t; cvta.to.shared.u64 t, %1; cvt.u32.u64 %0, t; }"
        : "=r"(sb) : "l"((const void*)smem));

    // decode upper-triangular tile index -> (bi, bj), bi <= bj
    int t = blockIdx.x, bi = 0;
    while (t >= NTILE - bi) { t -= NTILE - bi; bi++; }
    const int bj = bi + t;
    const bool diag = (bi == bj);
    const int rowBase = bi * 128;
    const int colBase = bj * 128;

    const int tid  = threadIdx.x;
    const int wid  = tid >> 5;
    const int lane = tid & 31;
    const int warp_m = wid & 3;      // 32 rows each
    const int warp_n = wid >> 2;     // 64 cols each

    const __nv_bfloat16* Z = (const __nv_bfloat16*)g_znb4;

    float acc[2][8][4];
#pragma unroll
    for (int mi = 0; mi < 2; mi++)
#pragma unroll
        for (int ni = 0; ni < 8; ni++)
#pragma unroll
            for (int r = 0; r < 4; r++) acc[mi][ni][r] = 0.0f;

    // stage loader: 2048 16B chunks (A:1024, B:1024), 8 per thread
    auto load_stage = [&](int st) {
        const int buf = st & 1;
#pragma unroll
        for (int l = 0; l < 8; l++) {
            int ch  = tid + l * 256;
            int isB = ch >> 10;
            int idx = ch & 1023;
            int r = idx >> 3, c = idx & 7;
            uint32_t dst = sb + (isB ? OFF_B : OFF_A) + buf * STG
                         + sw128((uint32_t)(r * 128 + c * 16));
            const void* src = Z + (size_t)((isB ? colBase : rowBase) + r) * DDIM
                            + st * BKS + c * 8;
            cp_async16(dst, src);
        }
        cp_commit();
    };

    load_stage(0);

    for (int st = 0; st < NKT; st++) {
        if (st + 1 < NKT) { load_stage(st + 1); cp_wait1(); }
        else              { cp_wait0(); }
        __syncthreads();

        const uint32_t aBase = sb + OFF_A + (st & 1) * STG;
        const uint32_t bBase = sb + OFF_B + (st & 1) * STG;
#pragma unroll
        for (int ks = 0; ks < 4; ks++) {          // four k16 sub-steps
            uint32_t a[2][4];
#pragma unroll
            for (int mi = 0; mi < 2; mi++) {
                int r = warp_m * 32 + mi * 16 + (lane & 15);
                uint32_t ad = aBase + sw128((uint32_t)(r * 128 + ks * 32 + (lane >> 4) * 16));
                ldm_x4(ad, a[mi][0], a[mi][1], a[mi][2], a[mi][3]);
            }
            uint32_t b[8][2];
#pragma unroll
            for (int p = 0; p < 4; p++) {
                int nrow = warp_n * 64 + p * 16 + (lane >> 4) * 8 + (lane & 7);
                uint32_t ad = bBase + sw128((uint32_t)(nrow * 128 + ks * 32 + ((lane >> 3) & 1) * 16));
                uint32_t r0, r1, r2, r3;
                ldm_x4(ad, r0, r1, r2, r3);
                b[2*p][0] = r0;   b[2*p][1] = r1;
                b[2*p+1][0] = r2; b[2*p+1][1] = r3;
            }
#pragma unroll
            for (int mi = 0; mi < 2; mi++)
#pragma unroll
                for (int ni = 0; ni < 8; ni++)
                    mma16816(acc[mi][ni][0], acc[mi][ni][1], acc[mi][ni][2], acc[mi][ni][3],
                             a[mi][0], a[mi][1], a[mi][2], a[mi][3],
                             b[ni][0], b[ni][1]);
        }
        __syncthreads();
    }

    // ---- Epilogue (proven round-5 structure).
    float colsum[8][2];
#pragma unroll
    for (int ni = 0; ni < 8; ni++) { colsum[ni][0] = 0.0f; colsum[ni][1] = 0.0f; }

#pragma unroll
    for (int mi = 0; mi < 2; mi++) {
#pragma unroll
        for (int half = 0; half < 2; half++) {
            int row = rowBase + warp_m * 32 + mi * 16 + half * 8 + (lane >> 2);
            float s = 0.0f;
#pragma unroll
            for (int ni = 0; ni < 8; ni++) {
#pragma unroll
                for (int cc = 0; cc < 2; cc++) {
                    int col = colBase + warp_n * 64 + ni * 8 + 2 * (lane & 3) + cc;
                    float v = acc[mi][ni][half * 2 + cc] * INV_T;
                    if (col == row + BSZ) { g_pos[row] = v; g_pos[col] = v; }
                    float e = __expf(v - 2.0f);
                    if (!diag || col != row) s += e;
                    colsum[ni][cc] += e;
                }
            }
            s += __shfl_xor_sync(0xFFFFFFFFu, s, 1);
            s += __shfl_xor_sync(0xFFFFFFFFu, s, 2);
            if ((lane & 3) == 0) atomicAdd(&g_rowsum[row], s);
        }
    }

    if (!diag) {
#pragma unroll
        for (int ni = 0; ni < 8; ni++) {
#pragma unroll
            for (int cc = 0; cc < 2; cc++) {
                float s = colsum[ni][cc];
                s += __shfl_xor_sync(0xFFFFFFFFu, s, 4);
                s += __shfl_xor_sync(0xFFFFFFFFu, s, 8);
                s += __shfl_xor_sync(0xFFFFFFFFu, s, 16);
                if (lane < 4) {
                    int col = colBase + warp_n * 64 + ni * 8 + 2 * lane + cc;
                    atomicAdd(&g_rowsum[col], s);
                }
            }
        }
    }

    // ---- last-CTA finalize
    __threadfence();
    __syncthreads();
    __shared__ unsigned s_last;
    if (tid == 0) s_last = (atomicAdd(&g_done, 1u) == NTRI - 1) ? 1u : 0u;
    __syncthreads();
    if (s_last) {
        __shared__ float red[256];
        float s = 0.0f;
        for (int i = tid; i < NTOT; i += 256)
            s += 2.0f + logf(__ldcg(&g_rowsum[i])) - __ldcg(&g_pos[i]);
        red[tid] = s;
        __syncthreads();
#pragma unroll
        for (int o = 128; o; o >>= 1) {
            if (tid < o) red[tid] += red[tid + o];
            __syncthreads();
        }
        if (tid == 0) out[0] = red[0] * (1.0f / NTOT);
    }
}

extern "C" void kernel_launch(void* const* d_in, const int* in_sizes, int n_in,
                              void* d_out, int out_size) {
    const float* zi = (const float*)d_in[0];
    const float* zj = (const float*)d_in[1];
    float* out = (float*)d_out;
    (void)in_sizes; (void)n_in; (void)out_size;

    cudaFuncSetAttribute(nt_mma, cudaFuncAttributeMaxDynamicSharedMemorySize, SMEM_TOTAL);

    nt_normalize<<<NTOT / 8, 256>>>(zi, zj);
    nt_mma<<<NTRI, 256, SMEM_TOTAL>>>(out);
}